// round 14
// baseline (speedup 1.0000x reference)
#include <cuda_runtime.h>
#include <math_constants.h>
#include <cstdint>

#define NROWS 100000
#define DIM   1024
#define RNUM  64

#define SEG        1024
#define NSEG_CKPT  97          // boundaries at rows 1024..99328

// colsum pipeline: 32 blocks x 32 cols, 256-row tiles, 5-stage ring,
// issue distance 3, ONE barrier per tile
#define CS_BLOCKS 32
#define CS_COLS   32
#define CS_T      256
#define CS_S      5
#define CS_SMEM   (CS_S * CS_T * CS_COLS * 4)   // 160 KB dynamic

// dots (R10 measured-best shape): 256 rows/block, 32-col smem chunks
#define DR   256
#define DCH  32
#define DBLK ((NROWS + DR - 1) / DR)    // 391
#define NKEYS   32

// -------- scratch (no allocations allowed) --------
__device__ float g_ckpt[NSEG_CKPT][DIM];  // chain state after rows [0,(s+1)*SEG)
__device__ float g_m[DIM];
__device__ float g_taken[NROWS];
__device__ int   g_takenList[RNUM];       // sorted ascending, distinct taken rows
__device__ int   g_nTaken;
__device__ int   g_remaining;
__device__ int   g_restartSeg;            // first segment whose chain changed
__device__ unsigned long long g_bestK[NKEYS];  // packed (enc(score) << 32) | ~idx
__device__ unsigned int g_doneCtr;
__device__ int   g_sel[RNUM];
__device__ int   g_selSorted[RNUM];

// monotone float encoding; ties -> smaller idx wins via ~idx in low bits
__device__ __forceinline__ unsigned long long pack_key(float s, int idx) {
    unsigned b = __float_as_uint(s);
    b = (b & 0x80000000u) ? ~b : (b | 0x80000000u);
    return ((unsigned long long)b << 32) | (unsigned)(0xffffffffu - (unsigned)idx);
}

// -------- init (graph replays must fully reset state) --------
__global__ void init_kernel() {
    int i = blockIdx.x * blockDim.x + threadIdx.x;
    if (i < NROWS) g_taken[i] = 0.0f;
    if (i < NKEYS) g_bestK[i] = 0ull;
    if (i == 0) { g_remaining = NROWS; g_nTaken = 0; g_restartSeg = 0; g_doneCtr = 0u; }
}

__device__ __forceinline__ void cp_async16(uint32_t saddr, const float* gptr) {
    asm volatile("cp.async.ca.shared.global [%0], [%1], 16;" :: "r"(saddr), "l"(gptr));
}

// producers (threads 32..255): issue one 256-row x 32-col tile (2048 x 16B)
__device__ __forceinline__ void cs_issue(const float* __restrict__ x, uint32_t bufAddr,
                                         int rStart, int ti, int colBase, int t) {
    int r0 = rStart + ti * CS_T;
    int st = ti % CS_S;
    uint32_t stBase = bufAddr + (uint32_t)(st * CS_T * CS_COLS * 4);
    int p = t - 32;                       // 0..223
#pragma unroll 3
    for (int op = p; op < CS_T * 8; op += 224) {
        int row = op >> 3;
        int ch  = op & 7;
        int gr = r0 + row;
        if (gr < NROWS)
            cp_async16(stBase + (uint32_t)((row * CS_COLS + ch * 4) * 4),
                       x + (size_t)gr * DIM + colBase + ch * 4);
    }
}

// -------- colsum: bit-exact sequential fadd chain per column (validated R8-R13).
// Single barrier per tile: 5-stage ring with issue distance 3, so the stage
// written at iter i ((i+3)%5) never aliases the stages read ((i-1)%5, i%5). --
__global__ void __launch_bounds__(256) colsum_kernel(const float* __restrict__ x) {
    extern __shared__ float buf[];               // [CS_S][CS_T][CS_COLS]
    __shared__ int sList[RNUM];
    __shared__ int sMeta[3];

    int t = threadIdx.x;
    if (t == 0) { sMeta[0] = g_nTaken; sMeta[1] = g_restartSeg; sMeta[2] = g_remaining; }
    __syncthreads();
    int sN = sMeta[0], sSeg = sMeta[1], sRem = sMeta[2];
    if (t < RNUM && t < sN) sList[t] = g_takenList[t];
    __syncthreads();

    int colBase = blockIdx.x * CS_COLS;
    int rStart = sSeg << 10;
    int ntiles = (NROWS - rStart + CS_T - 1) / CS_T;   // tail >= 672 rows -> >= 3 tiles

    uint32_t bufAddr = (uint32_t)__cvta_generic_to_shared(buf);
    bool producer = (t >= 32);

    // prologue: tiles 0..2 in flight
#pragma unroll
    for (int ti = 0; ti < 3; ti++) {
        if (producer && ti < ntiles) cs_issue(x, bufAddr, rStart, ti, colBase, t);
        asm volatile("cp.async.commit_group;");
    }

    // consumer chain state (lanes 0..31 of warp 0)
    float acc = 0.0f;
    int p = 0, nxt = 0x7fffffff;
    if (t < CS_COLS) {
        if (sSeg > 0) acc = g_ckpt[sSeg - 1][colBase + t];
        while (p < sN && sList[p] < rStart) p++;
        nxt = (p < sN) ? sList[p] : 0x7fffffff;
    }

#define LOADB(arr, b) { _Pragma("unroll") \
    for (int j = 0; j < 16; j++) arr[j] = s[(((b) << 4) + j) * CS_COLS]; }
#define CHAINB(arr) { _Pragma("unroll") \
    for (int j = 0; j < 16; j++) acc = __fadd_rn(acc, arr[j]); }
#define CHAINB_CHK(arr, rb) { _Pragma("unroll") \
    for (int j = 0; j < 16; j++) { \
        int r = (rb) + j; \
        if (r == nxt) { p++; nxt = (p < sN) ? sList[p] : 0x7fffffff; } \
        else acc = __fadd_rn(acc, arr[j]); } }

    for (int i = 0; i < ntiles; i++) {
        // issue tile i+3 into stage (i+3)%5 (disjoint from consumer's stages)
        if (producer && (i + 3) < ntiles)
            cs_issue(x, bufAddr, rStart, i + 3, colBase, t);
        asm volatile("cp.async.commit_group;");
        // producers: own 3 newer groups pending -> waits until tile i's data landed
        asm volatile("cp.async.wait_group 3;");
        __syncthreads();                         // publishes tile i to consumer

        if (t < CS_COLS) {
            const float* s = buf + (i % CS_S) * CS_T * CS_COLS + t;
            int r0 = rStart + i * CS_T;
            int nr = min(CS_T, NROWS - r0);      // always a multiple of 16
            int nb = nr >> 4;
            float v0[16], v1[16];
            LOADB(v0, 0)
            for (int b = 0; b < nb; b++) {
                int rb = r0 + (b << 4);
                bool clean = (nxt >= rb + 16);
                if (b & 1) {
                    if (b + 1 < nb) LOADB(v0, b + 1)
                    if (clean) CHAINB(v1) else CHAINB_CHK(v1, rb)
                } else {
                    if (b + 1 < nb) LOADB(v1, b + 1)
                    if (clean) CHAINB(v0) else CHAINB_CHK(v0, rb)
                }
            }
            if (((r0 + nr) & (SEG - 1)) == 0)
                g_ckpt[((r0 + nr) >> 10) - 1][colBase + t] = acc;
        }
    }
    asm volatile("cp.async.wait_group 0;");
    if (t < CS_COLS)
        g_m[colBase + t] = __fdiv_rn(acc, (float)sRem);
}

// -------- dots + argmax + fused finalize: R10 measured-best smem shape.
// Eigen 4-chain FMA order (validated); ms loaded once; last block finalizes. --
__global__ void __launch_bounds__(DR) dots_argmax_kernel(const float* __restrict__ x, int k) {
    __shared__ float tile[DR][DCH + 1];      // stride 33: conflict-free
    __shared__ float ms[DIM];
    __shared__ float sSc[DR];
    __shared__ int   sIx[DR];

    int t = threadIdx.x;
    int row0 = blockIdx.x * DR;
    int row = row0 + t;
    bool valid = row < NROWS;

    for (int i = t; i < DIM; i += DR) ms[i] = g_m[i];

    float a0 = 0.0f, a1 = 0.0f, a2 = 0.0f, a3 = 0.0f;

    for (int cb = 0; cb < DIM / DCH; cb++) {
        for (int i = t; i < DR * DCH; i += DR) {
            int r = i >> 5;
            int c = i & (DCH - 1);
            int gr = row0 + r;
            tile[r][c] = (gr < NROWS) ? x[(size_t)gr * DIM + cb * DCH + c] : 0.0f;
        }
        __syncthreads();
        if (valid) {
            const float* tr = tile[t];
            const float* mc = ms + cb * DCH;
#pragma unroll
            for (int c = 0; c < DCH; c += 4) {
                a0 = __fmaf_rn(tr[c + 0], mc[c + 0], a0);
                a1 = __fmaf_rn(tr[c + 1], mc[c + 1], a1);
                a2 = __fmaf_rn(tr[c + 2], mc[c + 2], a2);
                a3 = __fmaf_rn(tr[c + 3], mc[c + 3], a3);
            }
        }
        __syncthreads();
    }

    float score = -CUDART_INF_F;
    if (valid) {
        float dot = __fadd_rn(__fadd_rn(a0, a1), __fadd_rn(a2, a3));
        score = __fadd_rn(__fdiv_rn(1.0f, dot), g_taken[row]);
    }
    sSc[t] = score;
    sIx[t] = row;
    __syncthreads();
    for (int off = DR / 2; off > 0; off >>= 1) {
        if (t < off) {
            float s = sSc[t + off];
            int  id = sIx[t + off];
            if (s > sSc[t] || (s == sSc[t] && id < sIx[t])) { sSc[t] = s; sIx[t] = id; }
        }
        __syncthreads();
    }

    if (t == 0) {
        atomicMax(&g_bestK[blockIdx.x & (NKEYS - 1)], pack_key(sSc[0], sIx[0]));
        __threadfence();
        unsigned prev = atomicAdd(&g_doneCtr, 1u);
        if (prev == (unsigned)(DBLK - 1)) {
            __threadfence();
            // -------- fused finalize (deterministic: max over all published keys)
            unsigned long long key = 0ull;
#pragma unroll
            for (int i = 0; i < NKEYS; i++) {
                unsigned long long v = g_bestK[i];
                if (v > key) key = v;
                g_bestK[i] = 0ull;             // reset for next iteration
            }
            int w = (int)(0xffffffffu - (unsigned)(key & 0xffffffffu));
            g_sel[k] = w;
            float tv = g_taken[w];
            g_taken[w] = __fadd_rn(tv, -100000.0f);
            if (tv == 0.0f) {
                g_remaining -= 1;
                int n = g_nTaken;
                int pos = n;
                while (pos > 0 && g_takenList[pos - 1] > w) {
                    g_takenList[pos] = g_takenList[pos - 1];
                    pos--;
                }
                g_takenList[pos] = w;
                g_nTaken = n + 1;
            }
            g_restartSeg = w >> 10;            // chain changes from row w onward
            g_doneCtr = 0u;
        }
    }
}

// -------- epilogue: rank sort (duplicate-safe), gather rows --------
__global__ void sortsel_kernel() {
    int t = threadIdx.x;            // 64 threads
    int v = g_sel[t];
    int r = 0;
    for (int j = 0; j < RNUM; j++) {
        int u = g_sel[j];
        r += (u < v) || (u == v && j < t);
    }
    g_selSorted[r] = v;
}

__global__ void gather_kernel(const float* __restrict__ x, float* __restrict__ out) {
    int row = g_selSorted[blockIdx.x];
    const float4* src = (const float4*)(x + (size_t)row * DIM);
    float4* dst = (float4*)(out + (size_t)blockIdx.x * DIM);
    dst[threadIdx.x] = src[threadIdx.x];   // 256 threads x float4 = 1024 floats
}

extern "C" void kernel_launch(void* const* d_in, const int* in_sizes, int n_in,
                              void* d_out, int out_size) {
    const float* x = (const float*)d_in[0];
    float* out = (float*)d_out;

    cudaFuncSetAttribute(colsum_kernel,
                         cudaFuncAttributeMaxDynamicSharedMemorySize, CS_SMEM);

    init_kernel<<<(NROWS + 255) / 256, 256>>>();

    for (int k = 0; k < RNUM; k++) {
        colsum_kernel<<<CS_BLOCKS, 256, CS_SMEM>>>(x);
        dots_argmax_kernel<<<DBLK, DR>>>(x, k);
    }

    sortsel_kernel<<<1, RNUM>>>();
    gather_kernel<<<RNUM, 256>>>(x, out);
}

// round 15
// speedup vs baseline: 1.2639x; 1.2639x over previous
#include <cuda_runtime.h>
#include <math_constants.h>
#include <cstdint>

#define NROWS 100000
#define DIM   1024
#define RNUM  64

#define SEG        1024
#define NSEG_CKPT  97          // boundaries at rows 1024..99328

// colsum pipeline: 128 blocks x 8 cols, 256-row tiles, 4-stage cp.async ring.
// 8 cols/block => 200k cp.async ops per block per full pass: issue (~110us)
// now sits BELOW the serial-chain floor (~222us) -> chain-bound, the true floor.
#define CS_BLOCKS 128
#define CS_COLS   8
#define CS_T      256
#define CS_S      4
#define CS_SMEM   (CS_S * CS_T * CS_COLS * 4)   // 32 KB dynamic

// dots (R10 measured-best shape): 256 rows/block, 32-col smem chunks
#define DR   256
#define DCH  32
#define DBLK ((NROWS + DR - 1) / DR)    // 391

// -------- scratch (no allocations allowed) --------
__device__ float g_ckpt[NSEG_CKPT][DIM];  // chain state after rows [0,(s+1)*SEG)
__device__ float g_m[DIM];
__device__ float g_taken[NROWS];
__device__ int   g_takenList[RNUM];       // sorted ascending, distinct taken rows
__device__ int   g_nTaken;
__device__ int   g_remaining;
__device__ int   g_restartSeg;            // first segment whose chain changed
__device__ float g_bScore[DBLK];
__device__ int   g_bIdx[DBLK];
__device__ int   g_sel[RNUM];
__device__ int   g_selSorted[RNUM];

// -------- init (graph replays must fully reset state) --------
__global__ void init_kernel() {
    int i = blockIdx.x * blockDim.x + threadIdx.x;
    if (i < NROWS) g_taken[i] = 0.0f;
    if (i == 0) { g_remaining = NROWS; g_nTaken = 0; g_restartSeg = 0; }
}

__device__ __forceinline__ void cp_async16(uint32_t saddr, const float* gptr) {
    asm volatile("cp.async.ca.shared.global [%0], [%1], 16;" :: "r"(saddr), "l"(gptr));
}

// producers (threads 32..255): issue one 256-row x 8-col tile (512 x 16B)
__device__ __forceinline__ void cs_issue(const float* __restrict__ x, uint32_t bufAddr,
                                         int rStart, int ti, int colBase, int t) {
    int r0 = rStart + ti * CS_T;
    int st = ti & (CS_S - 1);
    uint32_t stBase = bufAddr + (uint32_t)(st * CS_T * CS_COLS * 4);
    int p = t - 32;                       // 0..223
#pragma unroll 3
    for (int op = p; op < CS_T * 2; op += 224) {
        int row = op >> 1;
        int ch  = op & 1;
        int gr = r0 + row;
        if (gr < NROWS)
            cp_async16(stBase + (uint32_t)((row * CS_COLS + ch * 4) * 4),
                       x + (size_t)gr * DIM + colBase + ch * 4);
    }
}

// -------- colsum: bit-exact sequential fadd chain per column (validated R8-R14),
// warp-specialized: warps 1-7 produce via cp.async ring, warp 0 lanes 0-7 = chains.
__global__ void __launch_bounds__(256) colsum_kernel(const float* __restrict__ x) {
    extern __shared__ float buf[];               // [CS_S][CS_T][CS_COLS]
    __shared__ int sList[RNUM];
    __shared__ int sMeta[3];

    int t = threadIdx.x;
    if (t == 0) { sMeta[0] = g_nTaken; sMeta[1] = g_restartSeg; sMeta[2] = g_remaining; }
    __syncthreads();
    int sN = sMeta[0], sSeg = sMeta[1], sRem = sMeta[2];
    if (t < RNUM && t < sN) sList[t] = g_takenList[t];
    __syncthreads();

    int colBase = blockIdx.x * CS_COLS;
    int rStart = sSeg << 10;
    int ntiles = (NROWS - rStart + CS_T - 1) / CS_T;

    uint32_t bufAddr = (uint32_t)__cvta_generic_to_shared(buf);
    bool producer = (t >= 32);

    // prologue: tiles 0..2 in flight
#pragma unroll
    for (int ti = 0; ti < CS_S - 1; ti++) {
        if (producer && ti < ntiles) cs_issue(x, bufAddr, rStart, ti, colBase, t);
        asm volatile("cp.async.commit_group;");
    }

    // consumer chain state (lanes 0..7 of warp 0)
    float acc = 0.0f;
    int p = 0, nxt = 0x7fffffff;
    if (t < CS_COLS) {
        if (sSeg > 0) acc = g_ckpt[sSeg - 1][colBase + t];
        while (p < sN && sList[p] < rStart) p++;
        nxt = (p < sN) ? sList[p] : 0x7fffffff;
    }

    for (int i = 0; i < ntiles; i++) {
        asm volatile("cp.async.wait_group 2;");  // tile i complete
        __syncthreads();
        if (producer && (i + CS_S - 1) < ntiles)
            cs_issue(x, bufAddr, rStart, i + CS_S - 1, colBase, t);
        asm volatile("cp.async.commit_group;");

        if (t < CS_COLS) {
            const float* s = buf + (i & (CS_S - 1)) * CS_T * CS_COLS + t;
            int r0 = rStart + i * CS_T;
            int nr = min(CS_T, NROWS - r0);
            bool slow = (nr < CS_T) || (nxt < r0 + nr);
            if (!slow) {
                // pure chain, software-pipelined 16-row register batches
                float v0[16], v1[16];
#define LOADB(arr, b) { _Pragma("unroll") \
    for (int j = 0; j < 16; j++) arr[j] = s[(((b) << 4) + j) * CS_COLS]; }
#define CHAINB(arr) { _Pragma("unroll") \
    for (int j = 0; j < 16; j++) acc = __fadd_rn(acc, arr[j]); }
                LOADB(v0, 0)
#pragma unroll
                for (int b = 0; b < CS_T / 16; b++) {
                    if (b & 1) { if (b + 1 < CS_T / 16) LOADB(v0, b + 1) CHAINB(v1) }
                    else       { if (b + 1 < CS_T / 16) LOADB(v1, b + 1) CHAINB(v0) }
                }
                if (((r0 + CS_T) & (SEG - 1)) == 0)
                    g_ckpt[((r0 + CS_T) >> 10) - 1][colBase + t] = acc;
            } else {
                for (int j = 0; j < nr; j++) {
                    int r = r0 + j;
                    float v = s[j * CS_COLS];
                    if (r == nxt) { p++; nxt = (p < sN) ? sList[p] : 0x7fffffff; }
                    else acc = __fadd_rn(acc, v);
                    if (((r + 1) & (SEG - 1)) == 0)
                        g_ckpt[((r + 1) >> 10) - 1][colBase + t] = acc;
                }
            }
        }
        __syncthreads();
    }
    asm volatile("cp.async.wait_group 0;");
    if (t < CS_COLS)
        g_m[colBase + t] = __fdiv_rn(acc, (float)sRem);
}

// -------- dots + block argmax: Eigen 4-chain FMA order (validated R8-R14),
// R10 measured-best smem shape, verbatim. --------------------------------
__global__ void __launch_bounds__(DR) dots_argmax_kernel(const float* __restrict__ x) {
    __shared__ float tile[DR][DCH + 1];      // stride 33: conflict-free
    __shared__ float ms[DCH];
    __shared__ float sSc[DR];
    __shared__ int   sIx[DR];

    int t = threadIdx.x;
    int row0 = blockIdx.x * DR;
    int row = row0 + t;
    bool valid = row < NROWS;

    float a0 = 0.0f, a1 = 0.0f, a2 = 0.0f, a3 = 0.0f;

    for (int cb = 0; cb < DIM / DCH; cb++) {
        // load 256 rows x 32 cols as float4 (8 per thread), coalesced
#pragma unroll
        for (int f = 0; f < 8; f++) {
            int idx = t + f * DR;
            int r = idx >> 3;
            int c4 = idx & 7;
            int gr = row0 + r;
            float4 v = make_float4(0.f, 0.f, 0.f, 0.f);
            if (gr < NROWS)
                v = ((const float4*)(x + (size_t)gr * DIM + cb * DCH))[c4];
            tile[r][c4 * 4 + 0] = v.x;
            tile[r][c4 * 4 + 1] = v.y;
            tile[r][c4 * 4 + 2] = v.z;
            tile[r][c4 * 4 + 3] = v.w;
        }
        if (t < DCH) ms[t] = g_m[cb * DCH + t];
        __syncthreads();
        if (valid) {
#pragma unroll
            for (int c = 0; c < DCH; c += 4) {
                a0 = __fmaf_rn(tile[t][c + 0], ms[c + 0], a0);
                a1 = __fmaf_rn(tile[t][c + 1], ms[c + 1], a1);
                a2 = __fmaf_rn(tile[t][c + 2], ms[c + 2], a2);
                a3 = __fmaf_rn(tile[t][c + 3], ms[c + 3], a3);
            }
        }
        __syncthreads();
    }

    float score = -CUDART_INF_F;
    if (valid) {
        float dot = __fadd_rn(__fadd_rn(a0, a1), __fadd_rn(a2, a3));
        score = __fadd_rn(__fdiv_rn(1.0f, dot), g_taken[row]);
    }
    sSc[t] = score;
    sIx[t] = row;
    __syncthreads();
    for (int off = DR / 2; off > 0; off >>= 1) {
        if (t < off) {
            float s = sSc[t + off];
            int  id = sIx[t + off];
            if (s > sSc[t] || (s == sSc[t] && id < sIx[t])) { sSc[t] = s; sIx[t] = id; }
        }
        __syncthreads();
    }
    if (t == 0) { g_bScore[blockIdx.x] = sSc[0]; g_bIdx[blockIdx.x] = sIx[0]; }
}

// -------- finalize: global argmax over 391 blocks; maintain taken state -----
__global__ void finalize_kernel(int k) {
    __shared__ float sSc[256];
    __shared__ int   sIx[256];

    float best = -CUDART_INF_F;
    int   bi = 0x7fffffff;
    for (int i = threadIdx.x; i < DBLK; i += 256) {
        float s = g_bScore[i];
        int  id = g_bIdx[i];
        if (s > best || (s == best && id < bi)) { best = s; bi = id; }
    }
    sSc[threadIdx.x] = best;
    sIx[threadIdx.x] = bi;
    __syncthreads();
    for (int off = 128; off > 0; off >>= 1) {
        if (threadIdx.x < off) {
            float s = sSc[threadIdx.x + off];
            int  id = sIx[threadIdx.x + off];
            if (s > sSc[threadIdx.x] || (s == sSc[threadIdx.x] && id < sIx[threadIdx.x])) {
                sSc[threadIdx.x] = s;
                sIx[threadIdx.x] = id;
            }
        }
        __syncthreads();
    }
    if (threadIdx.x == 0) {
        int w = sIx[0];
        g_sel[k] = w;
        float t = g_taken[w];
        g_taken[w] = __fadd_rn(t, -100000.0f);
        if (t == 0.0f) {
            g_remaining -= 1;
            int n = g_nTaken;
            int pos = n;
            while (pos > 0 && g_takenList[pos - 1] > w) {
                g_takenList[pos] = g_takenList[pos - 1];
                pos--;
            }
            g_takenList[pos] = w;
            g_nTaken = n + 1;
        }
        g_restartSeg = w >> 10;   // chain changes from row w onward
    }
}

// -------- epilogue: rank sort (duplicate-safe), gather rows --------
__global__ void sortsel_kernel() {
    int t = threadIdx.x;            // 64 threads
    int v = g_sel[t];
    int r = 0;
    for (int j = 0; j < RNUM; j++) {
        int u = g_sel[j];
        r += (u < v) || (u == v && j < t);
    }
    g_selSorted[r] = v;
}

__global__ void gather_kernel(const float* __restrict__ x, float* __restrict__ out) {
    int row = g_selSorted[blockIdx.x];
    const float4* src = (const float4*)(x + (size_t)row * DIM);
    float4* dst = (float4*)(out + (size_t)blockIdx.x * DIM);
    dst[threadIdx.x] = src[threadIdx.x];   // 256 threads x float4 = 1024 floats
}

extern "C" void kernel_launch(void* const* d_in, const int* in_sizes, int n_in,
                              void* d_out, int out_size) {
    const float* x = (const float*)d_in[0];
    float* out = (float*)d_out;

    cudaFuncSetAttribute(colsum_kernel,
                         cudaFuncAttributeMaxDynamicSharedMemorySize, CS_SMEM);

    init_kernel<<<(NROWS + 255) / 256, 256>>>();

    for (int k = 0; k < RNUM; k++) {
        colsum_kernel<<<CS_BLOCKS, 256, CS_SMEM>>>(x);
        dots_argmax_kernel<<<DBLK, DR>>>(x);
        finalize_kernel<<<1, 256>>>(k);
    }

    sortsel_kernel<<<1, RNUM>>>();
    gather_kernel<<<RNUM, 256>>>(x, out);
}

// round 16
// speedup vs baseline: 1.6838x; 1.3322x over previous
#include <cuda_runtime.h>
#include <math_constants.h>
#include <cstdint>

#define NROWS 100000
#define DIM   1024
#define RNUM  64

#define SEG        1024
#define NSEG_CKPT  97          // boundaries at rows 1024..99328

// colsum pipeline: 32 blocks x 32 cols, 256-row tiles, 4-stage cp.async ring,
// fed from the TRANSPOSED copy (contiguous per-column streams).
#define CS_BLOCKS 32
#define CS_COLS   32
#define CS_T      256
#define CS_PAD    260          // floats per column in smem: 1040B, 16B-aligned
#define CS_S      4
#define CS_SMEM   (CS_S * CS_COLS * CS_PAD * 4)   // 133,120 B

// dots (R10 measured-best shape): 256 rows/block, 32-col smem chunks
#define DR   256
#define DCH  32
#define DBLK ((NROWS + DR - 1) / DR)    // 391

// -------- scratch (no allocations allowed) --------
__device__ float g_xT[DIM * NROWS];       // transposed x: column-major streams (400 MB)
__device__ float g_ckpt[NSEG_CKPT][DIM];  // chain state after rows [0,(s+1)*SEG)
__device__ float g_m[DIM];
__device__ float g_taken[NROWS];
__device__ int   g_takenList[RNUM];       // sorted ascending, distinct taken rows
__device__ int   g_nTaken;
__device__ int   g_remaining;
__device__ int   g_restartSeg;            // first segment whose chain changed
__device__ float g_bScore[DBLK];
__device__ int   g_bIdx[DBLK];
__device__ int   g_sel[RNUM];
__device__ int   g_selSorted[RNUM];

// -------- init (graph replays must fully reset state) --------
__global__ void init_kernel() {
    int i = blockIdx.x * blockDim.x + threadIdx.x;
    if (i < NROWS) g_taken[i] = 0.0f;
    if (i == 0) { g_remaining = NROWS; g_nTaken = 0; g_restartSeg = 0; }
}

// -------- one-time transpose: g_xT[c*NROWS + r] = x[r*DIM + c] --------------
// grid (32, 3125), block (32, 8); smem-tiled, both sides coalesced.
__global__ void transpose_kernel(const float* __restrict__ x) {
    __shared__ float tile[32][33];
    int cBase = blockIdx.x * 32;
    int rBase = blockIdx.y * 32;
    int tx = threadIdx.x, ty = threadIdx.y;
#pragma unroll
    for (int i = ty; i < 32; i += 8)
        tile[i][tx] = x[(size_t)(rBase + i) * DIM + cBase + tx];
    __syncthreads();
#pragma unroll
    for (int i = ty; i < 32; i += 8)
        g_xT[(size_t)(cBase + i) * NROWS + rBase + tx] = tile[tx][i];
}

__device__ __forceinline__ void cp_async16(uint32_t saddr, const float* gptr) {
    asm volatile("cp.async.ca.shared.global [%0], [%1], 16;" :: "r"(saddr), "l"(gptr));
}

// producers (threads 32..255): one 256-row x 32-col tile = 32 contiguous 1KB
// column chunks from g_xT (fully coalesced; NROWS%4==0 so 16B chunks are safe).
__device__ __forceinline__ void cs_issue(uint32_t bufAddr,
                                         int rStart, int ti, int colBase, int t) {
    int r0 = rStart + ti * CS_T;
    int st = ti & (CS_S - 1);
    uint32_t stBase = bufAddr + (uint32_t)(st * CS_COLS * CS_PAD * 4);
    int p = t - 32;                       // 0..223
#pragma unroll 3
    for (int q = p; q < CS_T / 4 * CS_COLS; q += 224) {   // 2048 ops
        int c  = q >> 6;                  // column 0..31
        int s4 = q & 63;                  // 16B chunk within column
        int gr = r0 + s4 * 4;
        if (gr < NROWS)
            cp_async16(stBase + (uint32_t)((c * CS_PAD + s4 * 4) * 4),
                       g_xT + (size_t)(colBase + c) * NROWS + gr);
    }
}

// -------- colsum: bit-exact sequential fadd chain per column (validated R8-R15),
// warp-specialized; smem tiles are col-major [col][CS_PAD]. ------------------
__global__ void __launch_bounds__(256) colsum_kernel() {
    extern __shared__ float buf[];               // [CS_S][CS_COLS][CS_PAD]
    __shared__ int sList[RNUM];
    __shared__ int sMeta[3];

    int t = threadIdx.x;
    if (t == 0) { sMeta[0] = g_nTaken; sMeta[1] = g_restartSeg; sMeta[2] = g_remaining; }
    __syncthreads();
    int sN = sMeta[0], sSeg = sMeta[1], sRem = sMeta[2];
    if (t < RNUM && t < sN) sList[t] = g_takenList[t];
    __syncthreads();

    int colBase = blockIdx.x * CS_COLS;
    int rStart = sSeg << 10;
    int ntiles = (NROWS - rStart + CS_T - 1) / CS_T;

    uint32_t bufAddr = (uint32_t)__cvta_generic_to_shared(buf);
    bool producer = (t >= 32);

    // prologue: tiles 0..2 in flight
#pragma unroll
    for (int ti = 0; ti < CS_S - 1; ti++) {
        if (producer && ti < ntiles) cs_issue(bufAddr, rStart, ti, colBase, t);
        asm volatile("cp.async.commit_group;");
    }

    // consumer chain state (lanes 0..31 of warp 0); lane t owns column colBase+t
    float acc = 0.0f;
    int p = 0, nxt = 0x7fffffff;
    if (t < CS_COLS) {
        if (sSeg > 0) acc = g_ckpt[sSeg - 1][colBase + t];
        while (p < sN && sList[p] < rStart) p++;
        nxt = (p < sN) ? sList[p] : 0x7fffffff;
    }

    for (int i = 0; i < ntiles; i++) {
        asm volatile("cp.async.wait_group 2;");  // tile i complete
        __syncthreads();
        if (producer && (i + CS_S - 1) < ntiles)
            cs_issue(bufAddr, rStart, i + CS_S - 1, colBase, t);
        asm volatile("cp.async.commit_group;");

        if (t < CS_COLS) {
            const float* s = buf + (i & (CS_S - 1)) * CS_COLS * CS_PAD + t * CS_PAD;
            int r0 = rStart + i * CS_T;
            int nr = min(CS_T, NROWS - r0);
            bool slow = (nr < CS_T) || (nxt < r0 + nr);
            if (!slow) {
                // pure chain, software-pipelined 16-row register batches
                float v0[16], v1[16];
#define LOADB(arr, b) { _Pragma("unroll") \
    for (int j = 0; j < 16; j++) arr[j] = s[((b) << 4) + j]; }
#define CHAINB(arr) { _Pragma("unroll") \
    for (int j = 0; j < 16; j++) acc = __fadd_rn(acc, arr[j]); }
                LOADB(v0, 0)
#pragma unroll
                for (int b = 0; b < CS_T / 16; b++) {
                    if (b & 1) { if (b + 1 < CS_T / 16) LOADB(v0, b + 1) CHAINB(v1) }
                    else       { if (b + 1 < CS_T / 16) LOADB(v1, b + 1) CHAINB(v0) }
                }
                if (((r0 + CS_T) & (SEG - 1)) == 0)
                    g_ckpt[((r0 + CS_T) >> 10) - 1][colBase + t] = acc;
            } else {
                for (int j = 0; j < nr; j++) {
                    int r = r0 + j;
                    float v = s[j];
                    if (r == nxt) { p++; nxt = (p < sN) ? sList[p] : 0x7fffffff; }
                    else acc = __fadd_rn(acc, v);
                    if (((r + 1) & (SEG - 1)) == 0)
                        g_ckpt[((r + 1) >> 10) - 1][colBase + t] = acc;
                }
            }
        }
        __syncthreads();
    }
    asm volatile("cp.async.wait_group 0;");
    if (t < CS_COLS)
        g_m[colBase + t] = __fdiv_rn(acc, (float)sRem);
}

// -------- dots + block argmax: Eigen 4-chain FMA order (validated R8-R15),
// R10 measured-best smem shape, verbatim. --------------------------------
__global__ void __launch_bounds__(DR) dots_argmax_kernel(const float* __restrict__ x) {
    __shared__ float tile[DR][DCH + 1];      // stride 33: conflict-free
    __shared__ float ms[DCH];
    __shared__ float sSc[DR];
    __shared__ int   sIx[DR];

    int t = threadIdx.x;
    int row0 = blockIdx.x * DR;
    int row = row0 + t;
    bool valid = row < NROWS;

    float a0 = 0.0f, a1 = 0.0f, a2 = 0.0f, a3 = 0.0f;

    for (int cb = 0; cb < DIM / DCH; cb++) {
        // load 256 rows x 32 cols as float4 (8 per thread), coalesced
#pragma unroll
        for (int f = 0; f < 8; f++) {
            int idx = t + f * DR;
            int r = idx >> 3;
            int c4 = idx & 7;
            int gr = row0 + r;
            float4 v = make_float4(0.f, 0.f, 0.f, 0.f);
            if (gr < NROWS)
                v = ((const float4*)(x + (size_t)gr * DIM + cb * DCH))[c4];
            tile[r][c4 * 4 + 0] = v.x;
            tile[r][c4 * 4 + 1] = v.y;
            tile[r][c4 * 4 + 2] = v.z;
            tile[r][c4 * 4 + 3] = v.w;
        }
        if (t < DCH) ms[t] = g_m[cb * DCH + t];
        __syncthreads();
        if (valid) {
#pragma unroll
            for (int c = 0; c < DCH; c += 4) {
                a0 = __fmaf_rn(tile[t][c + 0], ms[c + 0], a0);
                a1 = __fmaf_rn(tile[t][c + 1], ms[c + 1], a1);
                a2 = __fmaf_rn(tile[t][c + 2], ms[c + 2], a2);
                a3 = __fmaf_rn(tile[t][c + 3], ms[c + 3], a3);
            }
        }
        __syncthreads();
    }

    float score = -CUDART_INF_F;
    if (valid) {
        float dot = __fadd_rn(__fadd_rn(a0, a1), __fadd_rn(a2, a3));
        score = __fadd_rn(__fdiv_rn(1.0f, dot), g_taken[row]);
    }
    sSc[t] = score;
    sIx[t] = row;
    __syncthreads();
    for (int off = DR / 2; off > 0; off >>= 1) {
        if (t < off) {
            float s = sSc[t + off];
            int  id = sIx[t + off];
            if (s > sSc[t] || (s == sSc[t] && id < sIx[t])) { sSc[t] = s; sIx[t] = id; }
        }
        __syncthreads();
    }
    if (t == 0) { g_bScore[blockIdx.x] = sSc[0]; g_bIdx[blockIdx.x] = sIx[0]; }
}

// -------- finalize: global argmax over 391 blocks; maintain taken state -----
__global__ void finalize_kernel(int k) {
    __shared__ float sSc[256];
    __shared__ int   sIx[256];

    float best = -CUDART_INF_F;
    int   bi = 0x7fffffff;
    for (int i = threadIdx.x; i < DBLK; i += 256) {
        float s = g_bScore[i];
        int  id = g_bIdx[i];
        if (s > best || (s == best && id < bi)) { best = s; bi = id; }
    }
    sSc[threadIdx.x] = best;
    sIx[threadIdx.x] = bi;
    __syncthreads();
    for (int off = 128; off > 0; off >>= 1) {
        if (threadIdx.x < off) {
            float s = sSc[threadIdx.x + off];
            int  id = sIx[threadIdx.x + off];
            if (s > sSc[threadIdx.x] || (s == sSc[threadIdx.x] && id < sIx[threadIdx.x])) {
                sSc[threadIdx.x] = s;
                sIx[threadIdx.x] = id;
            }
        }
        __syncthreads();
    }
    if (threadIdx.x == 0) {
        int w = sIx[0];
        g_sel[k] = w;
        float t = g_taken[w];
        g_taken[w] = __fadd_rn(t, -100000.0f);
        if (t == 0.0f) {
            g_remaining -= 1;
            int n = g_nTaken;
            int pos = n;
            while (pos > 0 && g_takenList[pos - 1] > w) {
                g_takenList[pos] = g_takenList[pos - 1];
                pos--;
            }
            g_takenList[pos] = w;
            g_nTaken = n + 1;
        }
        g_restartSeg = w >> 10;   // chain changes from row w onward
    }
}

// -------- epilogue: rank sort (duplicate-safe), gather rows --------
__global__ void sortsel_kernel() {
    int t = threadIdx.x;            // 64 threads
    int v = g_sel[t];
    int r = 0;
    for (int j = 0; j < RNUM; j++) {
        int u = g_sel[j];
        r += (u < v) || (u == v && j < t);
    }
    g_selSorted[r] = v;
}

__global__ void gather_kernel(const float* __restrict__ x, float* __restrict__ out) {
    int row = g_selSorted[blockIdx.x];
    const float4* src = (const float4*)(x + (size_t)row * DIM);
    float4* dst = (float4*)(out + (size_t)blockIdx.x * DIM);
    dst[threadIdx.x] = src[threadIdx.x];   // 256 threads x float4 = 1024 floats
}

extern "C" void kernel_launch(void* const* d_in, const int* in_sizes, int n_in,
                              void* d_out, int out_size) {
    const float* x = (const float*)d_in[0];
    float* out = (float*)d_out;

    cudaFuncSetAttribute(colsum_kernel,
                         cudaFuncAttributeMaxDynamicSharedMemorySize, CS_SMEM);

    init_kernel<<<(NROWS + 255) / 256, 256>>>();
    transpose_kernel<<<dim3(DIM / 32, NROWS / 32), dim3(32, 8)>>>(x);

    for (int k = 0; k < RNUM; k++) {
        colsum_kernel<<<CS_BLOCKS, 256, CS_SMEM>>>();
        dots_argmax_kernel<<<DBLK, DR>>>(x);
        finalize_kernel<<<1, 256>>>(k);
    }

    sortsel_kernel<<<1, RNUM>>>();
    gather_kernel<<<RNUM, 256>>>(x, out);
}